// round 15
// baseline (speedup 1.0000x reference)
#include <cuda_runtime.h>
#include <stdint.h>

// Problem constants
#define NT    4000
#define NS    16
#define NR    512
#define NCOL  (NS * NR)          // 8192 columns
#define NCG   (NCOL / 4)         // 2048 float4 column-groups
#define TPB   256
#define CGBLK (NCG / TPB)        // 8 column-group blocks per array
#define NSEG  74                 // 70 segs of 54 + 4 segs of 55 (= 4000)
#define NBLK  (CGBLK * 2 * NSEG) // 1184 = 148 SMs x 8 blocks: ONE full wave
#define FIN_BLOCKS (NCOL / TPB)  // 32

// Per-column packed argmax accumulators (0 = x, 1 = y), merged via atomicMax.
// key = (float_bits(|v|max) << 32) | ~t : u64 max -> larger |v| wins; on ties
// the larger ~t (= smaller t) wins, matching jnp.argmax. Keys are always > 0,
// so zero is a valid identity; finalize_kernel self-resets for graph replay.
__device__ unsigned long long g_best[2][NCOL];
__device__ unsigned long long g_accum;
__device__ unsigned int       g_done;

// Kernel 1: 1184 blocks, exactly 8 resident blocks/SM (64 warps/SM), single
// balanced wave. Each thread scans its time segment of 4 adjacent columns of
// ONE array with float4 loads: every warp request is 512B of CONTIGUOUS
// lines (4x the burst size of the scalar variant) to raise DRAM efficiency.
// One array/thread keeps state at ~30 regs so the 8-block residency holds
// (enforced by __launch_bounds__(TPB, 8)).
__global__ __launch_bounds__(TPB, 8) void seg_argmax_kernel(
    const float* __restrict__ x, const float* __restrict__ y)
{
    const int tile = blockIdx.x;
    const int cgb  = tile & (CGBLK - 1);          // 0..7
    const int arr  = (tile >> 3) & 1;             // 0 = x, 1 = y
    const int seg  = tile >> 4;                   // 0..73
    const int t0   = 54 * seg + ((seg > 70) ? (seg - 70) : 0);
    const int len  = (seg < 70) ? 54 : 55;

    const int cg = cgb * TPB + threadIdx.x;       // 0..NCG-1
    const float* __restrict__ src = arr ? y : x;
    const float4* __restrict__ p  = (const float4*)src + (size_t)t0 * NCG + cg;

    float m0 = -1.f, m1 = -1.f, m2 = -1.f, m3 = -1.f;
    int   i0 = t0,   i1 = t0,   i2 = t0,   i3 = t0;

    #pragma unroll 4
    for (int i = 0; i < len; ++i) {
        const float4 v = p[(size_t)i * NCG];
        const int t = t0 + i;
        if (fabsf(v.x) > m0) i0 = t; m0 = fmaxf(fabsf(v.x), m0);
        if (fabsf(v.y) > m1) i1 = t; m1 = fmaxf(fabsf(v.y), m1);
        if (fabsf(v.z) > m2) i2 = t; m2 = fmaxf(fabsf(v.z), m2);
        if (fabsf(v.w) > m3) i3 = t; m3 = fmaxf(fabsf(v.w), m3);
    }

    unsigned long long* __restrict__ acc = g_best[arr];
    const int colb = 4 * cg;
    atomicMax(&acc[colb + 0],
        ((unsigned long long)__float_as_uint(m0) << 32) | (unsigned int)~i0);
    atomicMax(&acc[colb + 1],
        ((unsigned long long)__float_as_uint(m1) << 32) | (unsigned int)~i1);
    atomicMax(&acc[colb + 2],
        ((unsigned long long)__float_as_uint(m2) << 32) | (unsigned int)~i2);
    atomicMax(&acc[colb + 3],
        ((unsigned long long)__float_as_uint(m3) << 32) | (unsigned int)~i3);
}

// Kernel 2: O(1) per thread. Read per-column winners, self-reset them for the
// next graph replay, exact integer MSE, one atomicAdd per block, ticketed
// last block writes the scalar and resets the accumulator.
__global__ __launch_bounds__(TPB) void finalize_kernel(float* __restrict__ out)
{
    const int col = blockIdx.x * TPB + threadIdx.x;

    const unsigned long long bx = g_best[0][col];
    const unsigned long long by = g_best[1][col];
    g_best[0][col] = 0ull;
    g_best[1][col] = 0ull;

    const int tx = (int)(~(unsigned int)bx);
    const int ty = (int)(~(unsigned int)by);
    const long long d = (long long)tx - (long long)ty;
    unsigned long long sq = (unsigned long long)(d * d);

    #pragma unroll
    for (int off = 16; off > 0; off >>= 1)
        sq += __shfl_down_sync(0xffffffffu, sq, off);

    __shared__ unsigned long long warp_sums[TPB / 32];
    const int lane = threadIdx.x & 31;
    const int wid  = threadIdx.x >> 5;
    if (lane == 0) warp_sums[wid] = sq;
    __syncthreads();

    if (wid == 0) {
        unsigned long long v = (lane < TPB / 32) ? warp_sums[lane] : 0ull;
        #pragma unroll
        for (int off = 4; off > 0; off >>= 1)
            v += __shfl_down_sync(0xffffffffu, v, off);
        if (lane == 0) {
            atomicAdd(&g_accum, v);
            __threadfence();
            const unsigned int ticket = atomicAdd(&g_done, 1u);
            if (ticket == (unsigned int)(FIN_BLOCKS - 1)) {
                const unsigned long long total = atomicAdd(&g_accum, 0ull);
                out[0] = (float)((double)total / (double)NCOL);
                __threadfence();
                g_accum = 0ull;
                g_done  = 0u;
            }
        }
    }
}

extern "C" void kernel_launch(void* const* d_in, const int* in_sizes, int n_in,
                              void* d_out, int out_size)
{
    const float* x = (const float*)d_in[0];
    const float* y = (const float*)d_in[1];
    float* out = (float*)d_out;

    seg_argmax_kernel<<<NBLK, TPB>>>(x, y);
    finalize_kernel<<<FIN_BLOCKS, TPB>>>(out);
}

// round 16
// speedup vs baseline: 1.0042x; 1.0042x over previous
#include <cuda_runtime.h>
#include <stdint.h>

// Problem constants
#define NT    4000
#define NS    16
#define NR    512
#define NCOL  (NS * NR)          // 8192 columns
#define TPB   256
#define XBLK  (NCOL / TPB)       // 32 column-blocks
#define NSEG  37                 // 36 segs of 108 + 1 seg of 112 (= 4000)
#define SEG_LEN 108
#define NBLK  (XBLK * NSEG)      // 1184 = 148 SMs x 8 blocks: ONE full wave
#define COLS_PER_THREAD (NCOL / TPB)  // 32

// Per-column packed argmax accumulators (0 = x, 1 = y), merged via atomicMax.
// key = (float_bits(|v|max) << 32) | ~t : u64 max -> larger |v| wins; on ties
// the larger ~t (= smaller t) wins, matching jnp.argmax. Keys are always > 0,
// so zero is a valid identity; the epilogue self-resets all state so every
// graph replay starts clean.
__device__ unsigned long long g_best[2][NCOL];
__device__ unsigned int       g_done;

// Single kernel: the R14 scan (1184 blocks, 8 blocks/SM, 64 warps/SM, one
// balanced wave, scalar loads = one 128B line per warp request, unroll 8)
// plus a ticketed last-block epilogue that replaces the separate finalize
// launch (~2us wall saved).
__global__ __launch_bounds__(TPB, 8) void traveltime_kernel(
    const float* __restrict__ x, const float* __restrict__ y,
    float* __restrict__ out)
{
    const int tile = blockIdx.x;
    const int col  = (tile & (XBLK - 1)) * TPB + threadIdx.x;  // 0..NCOL-1
    const int seg  = tile >> 5;                                // 0..36
    const int t0   = seg * SEG_LEN;
    const int len  = (seg == NSEG - 1) ? (NT - t0) : SEG_LEN;  // 108 or 112

    const float* __restrict__ px = x + (size_t)t0 * NCOL + col;
    const float* __restrict__ py = y + (size_t)t0 * NCOL + col;

    float mx = -1.0f, my = -1.0f;
    int   ix = t0,    iy = t0;

    #pragma unroll 8
    for (int i = 0; i < len; ++i) {
        const float vx = fabsf(px[(size_t)i * NCOL]);
        const float vy = fabsf(py[(size_t)i * NCOL]);
        const int t = t0 + i;
        if (vx > mx) ix = t;
        mx = fmaxf(vx, mx);
        if (vy > my) iy = t;
        my = fmaxf(vy, my);
    }

    atomicMax(&g_best[0][col],
        ((unsigned long long)__float_as_uint(mx) << 32) | (unsigned int)~ix);
    atomicMax(&g_best[1][col],
        ((unsigned long long)__float_as_uint(my) << 32) | (unsigned int)~iy);

    // ---- Ticketed epilogue: only the last block to finish proceeds. ----
    __threadfence();            // make this thread's atomics globally visible
    __syncthreads();            // whole block done + fenced

    __shared__ bool s_last;
    if (threadIdx.x == 0)
        s_last = (atomicAdd(&g_done, 1u) == (unsigned int)(NBLK - 1));
    __syncthreads();
    if (!s_last) return;

    __threadfence();            // acquire: see all other blocks' atomics

    // Last block: 256 threads x 32 columns, L2-resident reads (the atomics
    // just wrote these lines). Exact integer MSE; self-reset for replay.
    unsigned long long sum = 0ull;
    #pragma unroll 8
    for (int k = 0; k < COLS_PER_THREAD; ++k) {
        const int c = k * TPB + threadIdx.x;
        const unsigned long long bx = g_best[0][c];
        const unsigned long long by = g_best[1][c];
        g_best[0][c] = 0ull;
        g_best[1][c] = 0ull;
        const int tx = (int)(~(unsigned int)bx);
        const int ty = (int)(~(unsigned int)by);
        const long long d = (long long)tx - (long long)ty;
        sum += (unsigned long long)(d * d);
    }

    #pragma unroll
    for (int off = 16; off > 0; off >>= 1)
        sum += __shfl_down_sync(0xffffffffu, sum, off);

    __shared__ unsigned long long warp_sums[TPB / 32];
    const int lane = threadIdx.x & 31;
    const int wid  = threadIdx.x >> 5;
    if (lane == 0) warp_sums[wid] = sum;
    __syncthreads();

    if (wid == 0) {
        unsigned long long v = (lane < TPB / 32) ? warp_sums[lane] : 0ull;
        #pragma unroll
        for (int off = 4; off > 0; off >>= 1)
            v += __shfl_down_sync(0xffffffffu, v, off);
        if (lane == 0) {
            out[0] = (float)((double)v / (double)NCOL);
            __threadfence();
            g_done = 0u;        // reset ticket for the next graph replay
        }
    }
}

extern "C" void kernel_launch(void* const* d_in, const int* in_sizes, int n_in,
                              void* d_out, int out_size)
{
    const float* x = (const float*)d_in[0];
    const float* y = (const float*)d_in[1];
    float* out = (float*)d_out;

    traveltime_kernel<<<NBLK, TPB>>>(x, y, out);
}

// round 17
// speedup vs baseline: 1.0457x; 1.0413x over previous
#include <cuda_runtime.h>
#include <stdint.h>

// Problem constants
#define NT    4000
#define NS    16
#define NR    512
#define NCOL  (NS * NR)            // 8192 columns
#define TPB   512
#define CPT   4                    // columns per thread
#define COLSPAN (TPB * CPT)        // 2048 cols = 8KB contiguous per row-iter
#define NCGRP (NCOL / COLSPAN)     // 4 column-groups
#define NSEG  74                   // 70 segs of 54 + 4 segs of 55 (= 4000)
#define NBLK  (NCGRP * 2 * NSEG)   // 592 = 148 SMs x 4 blocks: ONE full wave
#define FTPB  256
#define FIN_BLOCKS (NCOL / FTPB)   // 32

// Per-column packed argmax accumulators (0 = x, 1 = y), merged via atomicMax.
// key = (float_bits(|v|max) << 32) | ~t : u64 max -> larger |v| wins; on ties
// the larger ~t (= smaller t) wins, matching jnp.argmax. Keys are always > 0,
// so zero is a valid identity; finalize_kernel self-resets for graph replay.
__device__ unsigned long long g_best[2][NCOL];
__device__ unsigned long long g_accum;
__device__ unsigned int       g_done;

// Kernel 1: 592 blocks, 4 resident blocks/SM (64 warps/SM), single balanced
// wave. Each block scans its time segment of ONE array over a 2048-column
// group: per row-iteration the block's 512 threads x 4 scalar loads cover
// ONE CONTIGUOUS 8KB span (64 consecutive 128B lines) -- a spatially
// coherent burst for the DRAM controllers, unlike the 32KB-scattered window
// of the per-column variant (DRAM was 61.7% there). Scalar LDG.32 keeps the
// proven best instruction mix; unroll 2 -> 8 independent lines/warp.
__global__ __launch_bounds__(TPB, 4) void seg_argmax_kernel(
    const float* __restrict__ x, const float* __restrict__ y)
{
    const int tile = blockIdx.x;
    const int cgb  = tile & (NCGRP - 1);          // 0..3 column-group
    const int arr  = (tile >> 2) & 1;             // 0 = x, 1 = y
    const int seg  = tile >> 3;                   // 0..73
    const int t0   = 54 * seg + ((seg > 70) ? (seg - 70) : 0);
    const int len  = (seg < 70) ? 54 : 55;

    const float* __restrict__ src = arr ? y : x;
    const int col0 = cgb * COLSPAN + threadIdx.x;  // thread's first column
    const float* __restrict__ p = src + (size_t)t0 * NCOL + col0;

    float m0 = -1.f, m1 = -1.f, m2 = -1.f, m3 = -1.f;
    int   i0 = t0,   i1 = t0,   i2 = t0,   i3 = t0;

    #pragma unroll 2
    for (int i = 0; i < len; ++i) {
        const float* __restrict__ r = p + (size_t)i * NCOL;
        const float v0 = fabsf(r[0]);
        const float v1 = fabsf(r[TPB]);
        const float v2 = fabsf(r[2 * TPB]);
        const float v3 = fabsf(r[3 * TPB]);
        const int t = t0 + i;
        if (v0 > m0) i0 = t;
        m0 = fmaxf(v0, m0);
        if (v1 > m1) i1 = t;
        m1 = fmaxf(v1, m1);
        if (v2 > m2) i2 = t;
        m2 = fmaxf(v2, m2);
        if (v3 > m3) i3 = t;
        m3 = fmaxf(v3, m3);
    }

    unsigned long long* __restrict__ acc = g_best[arr];
    atomicMax(&acc[col0],
        ((unsigned long long)__float_as_uint(m0) << 32) | (unsigned int)~i0);
    atomicMax(&acc[col0 + TPB],
        ((unsigned long long)__float_as_uint(m1) << 32) | (unsigned int)~i1);
    atomicMax(&acc[col0 + 2 * TPB],
        ((unsigned long long)__float_as_uint(m2) << 32) | (unsigned int)~i2);
    atomicMax(&acc[col0 + 3 * TPB],
        ((unsigned long long)__float_as_uint(m3) << 32) | (unsigned int)~i3);
}

// Kernel 2: O(1) per thread. Read per-column winners, self-reset them for the
// next graph replay, exact integer MSE, one atomicAdd per block, ticketed
// last block writes the scalar and resets the accumulator.
__global__ __launch_bounds__(FTPB) void finalize_kernel(float* __restrict__ out)
{
    const int col = blockIdx.x * FTPB + threadIdx.x;

    const unsigned long long bx = g_best[0][col];
    const unsigned long long by = g_best[1][col];
    g_best[0][col] = 0ull;
    g_best[1][col] = 0ull;

    const int tx = (int)(~(unsigned int)bx);
    const int ty = (int)(~(unsigned int)by);
    const long long d = (long long)tx - (long long)ty;
    unsigned long long sq = (unsigned long long)(d * d);

    #pragma unroll
    for (int off = 16; off > 0; off >>= 1)
        sq += __shfl_down_sync(0xffffffffu, sq, off);

    __shared__ unsigned long long warp_sums[FTPB / 32];
    const int lane = threadIdx.x & 31;
    const int wid  = threadIdx.x >> 5;
    if (lane == 0) warp_sums[wid] = sq;
    __syncthreads();

    if (wid == 0) {
        unsigned long long v = (lane < FTPB / 32) ? warp_sums[lane] : 0ull;
        #pragma unroll
        for (int off = 4; off > 0; off >>= 1)
            v += __shfl_down_sync(0xffffffffu, v, off);
        if (lane == 0) {
            atomicAdd(&g_accum, v);
            __threadfence();
            const unsigned int ticket = atomicAdd(&g_done, 1u);
            if (ticket == (unsigned int)(FIN_BLOCKS - 1)) {
                const unsigned long long total = atomicAdd(&g_accum, 0ull);
                out[0] = (float)((double)total / (double)NCOL);
                __threadfence();
                g_accum = 0ull;
                g_done  = 0u;
            }
        }
    }
}

extern "C" void kernel_launch(void* const* d_in, const int* in_sizes, int n_in,
                              void* d_out, int out_size)
{
    const float* x = (const float*)d_in[0];
    const float* y = (const float*)d_in[1];
    float* out = (float*)d_out;

    seg_argmax_kernel<<<NBLK, TPB>>>(x, y);
    finalize_kernel<<<FIN_BLOCKS, FTPB>>>(out);
}